// round 3
// baseline (speedup 1.0000x reference)
#include <cuda_runtime.h>
#include <cstdint>

#define N_PTS   131072
#define C_DIM   64
#define K_CB    512
#define NQ      4
#define HW_SZ   16384
#define P_BLK   64
#define NTHR    256
#define IDX_OFF 8388608
#define LOSS_OFF 8912896

// Scratch (allocation-free rule: __device__ globals)
__device__ float  g_G[K_CB * K_CB];   // Gram matrix cb @ cb.T (fast path only)
__device__ float  g_h[K_CB];          // 0.5 * ||cb_k||^2      (fast path only)
__device__ float  g_csq[K_CB];        // ||cb_k||^2, XLA-CPU vectorized-reduce order
__device__ double g_loss[NQ];         // double loss accumulators

// ---------------------------------------------------------------------------
// Precompute G, h, csq; zero loss accumulators.
// grid = 512 blocks x 64 threads. Block i computes row i of G.
// ---------------------------------------------------------------------------
__global__ void prep_kernel(const float* __restrict__ cb) {
    __shared__ float ci[C_DIM];
    const int i = blockIdx.x;
    const int t = threadIdx.x;
    ci[t] = cb[i * C_DIM + t];
    __syncthreads();
#pragma unroll
    for (int kk = 0; kk < 8; kk++) {
        const int k = t * 8 + kk;
        const float4* row = (const float4*)(cb + k * C_DIM);
        float s = 0.f;
#pragma unroll
        for (int c4 = 0; c4 < 16; c4++) {
            float4 v = row[c4];
            s = fmaf(ci[4 * c4 + 0], v.x, s);
            s = fmaf(ci[4 * c4 + 1], v.y, s);
            s = fmaf(ci[4 * c4 + 2], v.z, s);
            s = fmaf(ci[4 * c4 + 3], v.w, s);
        }
        g_G[i * K_CB + k] = s;
        if (k == i) g_h[i] = 0.5f * s;
    }
    if (t == 0) {
        // csq exactly as XLA:CPU vectorized reduce (NEON width 4):
        // 4 strided lane accumulators over contiguous float4 groups,
        // strict per-op rounding (separate mul + add, no FMA), then
        // shuffle-halving horizontal sum: (L0+L2) + (L1+L3).
        float l0 = 0.f, l1 = 0.f, l2 = 0.f, l3 = 0.f;
        for (int j = 0; j < 16; j++) {
            float v0 = ci[4 * j + 0], v1 = ci[4 * j + 1];
            float v2 = ci[4 * j + 2], v3 = ci[4 * j + 3];
            l0 = __fadd_rn(l0, __fmul_rn(v0, v0));
            l1 = __fadd_rn(l1, __fmul_rn(v1, v1));
            l2 = __fadd_rn(l2, __fmul_rn(v2, v2));
            l3 = __fadd_rn(l3, __fmul_rn(v3, v3));
        }
        g_csq[i] = __fadd_rn(__fadd_rn(l0, l2), __fadd_rn(l1, l3));
    }
    if (i == 0 && t < NQ) g_loss[t] = 0.0;
}

// Orderable-float packing: larger float -> larger uint (monotone).
__device__ __forceinline__ unsigned ford(float f) {
    unsigned u = __float_as_uint(f);
    return (u & 0x80000000u) ? ~u : (u | 0x80000000u);
}
__device__ __forceinline__ float funord(unsigned s) {
    unsigned u = (s & 0x80000000u) ? (s ^ 0x80000000u) : ~s;
    return __uint_as_float(u);
}

// ---------------------------------------------------------------------------
// Main fused RVQ kernel. Block = 64 points x 512 codewords.
// Fast Gram-cascade scores (registers) filter candidates; exact
// reference-order arithmetic decides the argmin among candidates.
// ---------------------------------------------------------------------------
__global__ __launch_bounds__(NTHR, 1)
void rvq_kernel(const float* __restrict__ x, const float* __restrict__ cb,
                float* __restrict__ out) {
    __shared__ float rs[C_DIM][P_BLK];          // exact residual, [c][p]
    __shared__ float cbs[8][520];               // codebook c-chunk, [c'][k]
    __shared__ unsigned red1[P_BLK];            // fast max per point
    __shared__ unsigned long long redmin[P_BLK];// packed (dist,k) argmin
    __shared__ int    idxs[NQ][P_BLK];
    __shared__ double sloss[NQ];

    const int tid   = threadIdx.x;
    const int pg    = tid & 7;
    const int kg    = tid >> 3;
    const int kbase = kg * 16;
    const int n0    = blockIdx.x * P_BLK;
    const int b     = n0 / HW_SZ;               // 64 | HW, block never crosses b
    const int hw0   = n0 % HW_SZ;
    const float* xbase = x + (size_t)b * C_DIM * HW_SZ + hw0;

    if (tid < P_BLK) { red1[tid] = 0u; redmin[tid] = ~0ull; }
    if (tid < NQ)    sloss[tid] = 0.0;

    // ---- load x tile (coalesced over p); rs starts as x (exact residual) ----
    {
        const int p  = tid & 63;
        const int cg = tid >> 6;
#pragma unroll
        for (int ii = 0; ii < 16; ii++) {
            const int c = cg * 16 + ii;
            rs[c][p] = xbase[(size_t)c * HW_SZ + p];
        }
    }

    // ---- fast scores: acc[k] = x.c - 0.5||c||^2 (candidate filter only) ----
    float acc[8][16];
    {
        float hv[16];
#pragma unroll
        for (int j4 = 0; j4 < 4; j4++)
            ((float4*)hv)[j4] = ((const float4*)(g_h + kbase))[j4];
#pragma unroll
        for (int i = 0; i < 8; i++)
#pragma unroll
            for (int j = 0; j < 16; j++)
                acc[i][j] = -hv[j];
    }
    for (int ct = 0; ct < 8; ct++) {
        __syncthreads();
        {   // load 8-channel slice of codebook, transposed to [c'][k]
            const int cp = tid & 7;
            const int k0 = tid >> 3;
#pragma unroll
            for (int it = 0; it < 16; it++) {
                const int k = k0 + 32 * it;
                cbs[cp][k] = cb[k * C_DIM + ct * 8 + cp];
            }
        }
        __syncthreads();
#pragma unroll
        for (int cc = 0; cc < 8; cc++) {
            const int c = ct * 8 + cc;
            float xa[8];
            ((float4*)xa)[0] = *((const float4*)&rs[c][pg * 8]);
            ((float4*)xa)[1] = *((const float4*)&rs[c][pg * 8 + 4]);
            float cv[16];
#pragma unroll
            for (int j4 = 0; j4 < 4; j4++)
                ((float4*)cv)[j4] = ((const float4*)&cbs[cc][kbase])[j4];
#pragma unroll
            for (int i = 0; i < 8; i++)
#pragma unroll
                for (int j = 0; j < 16; j++)
                    acc[i][j] = fmaf(xa[i], cv[j], acc[i][j]);
        }
    }
    __syncthreads();

    float  qsum[16];                 // quantized accumulator (per-thread channels)
#pragma unroll
    for (int ii = 0; ii < 16; ii++) qsum[ii] = 0.f;
    double lacc[NQ];
#pragma unroll
    for (int q = 0; q < NQ; q++) lacc[q] = 0.0;

    const int p_e  = tid & 63;       // elementwise-phase point
    const int cg_e = tid >> 6;       // elementwise-phase channel group

    // ---- 4 quantizer stages ----
#pragma unroll
    for (int q = 0; q < NQ; q++) {
        // A: fast local max per point -> red1
#pragma unroll
        for (int i = 0; i < 8; i++) {
            float bv = acc[i][0];
#pragma unroll
            for (int j = 1; j < 16; j++) bv = fmaxf(bv, acc[i][j]);
            atomicMax(&red1[pg * 8 + i], ford(bv));
        }
        __syncthreads();

        // B: exact (reference-order) dist for windowed candidates
#pragma unroll
        for (int i = 0; i < 8; i++) {
            const int p = pg * 8 + i;
            const float thr = funord(red1[p]) - 0.01f;
#pragma unroll
            for (int j = 0; j < 16; j++) {
                if (acc[i][j] >= thr) {
                    const int k = kbase + j;
                    const float* crow = cb + k * C_DIM;
                    float dot = 0.f;
#pragma unroll
                    for (int c = 0; c < C_DIM; c++)         // ascending-c seq FMA
                        dot = fmaf(rs[c][p], crow[c], dot);  // (Eigen gebp order)
                    float dist = __fsub_rn(g_csq[k], __fmul_rn(2.0f, dot));
                    unsigned long long pk =
                        ((unsigned long long)ford(dist) << 32) | (unsigned)k;
                    atomicMin(&redmin[p], pk);              // min dist, then min k
                }
            }
        }
        __syncthreads();

        // C: finalize pick, reset reducers
        if (tid < P_BLK) {
            idxs[q][tid] = (int)(unsigned)(redmin[tid] & 0xffffffffull);
            red1[tid]   = 0u;
            redmin[tid] = ~0ull;
        }
        __syncthreads();

        // D: exact elementwise update (replicates reference rounding chain)
        {
            const int k = idxs[q][p_e];
            const float* crow = cb + k * C_DIM;
            double ls = 0.0;
#pragma unroll
            for (int ii = 0; ii < 16; ii++) {
                const int c = cg_e * 16 + ii;
                const float cv = crow[c];
                const float r  = rs[c][p_e];
                const float d  = __fsub_rn(cv, r);          // quant - residual
                const float qst = __fadd_rn(r, d);          // straight-through
                qsum[ii] = __fadd_rn(qsum[ii], qst);        // quant_out += qst
                rs[c][p_e] = __fsub_rn(r, cv);              // residual -= quant
                const float sq = __fmul_rn(d, d);
                ls += (double)sq;
            }
            lacc[q] += ls;
        }

        // E: fast-score cascade for next stage: acc -= G[idx] row
        if (q < NQ - 1) {
#pragma unroll
            for (int i = 0; i < 8; i++) {
                const int row = idxs[q][pg * 8 + i];
                const float4* gr = (const float4*)(g_G + row * K_CB + kbase);
#pragma unroll
                for (int j4 = 0; j4 < 4; j4++) {
                    float4 g = gr[j4];
                    acc[i][4 * j4 + 0] -= g.x;
                    acc[i][4 * j4 + 1] -= g.y;
                    acc[i][4 * j4 + 2] -= g.z;
                    acc[i][4 * j4 + 3] -= g.w;
                }
            }
        }
        __syncthreads();
    }

    // ---- outputs ----
    // indices as float, coalesced: 256 threads cover 64 points x 4 stages
    {
        const int q = tid & 3, p = tid >> 2;
        out[IDX_OFF + (size_t)(n0 + p) * NQ + q] = (float)idxs[q][p];
    }
    // quantized in [B,C,H,W] layout (coalesced over p)
    {
        float* obase = out + (size_t)b * C_DIM * HW_SZ + hw0 + p_e;
#pragma unroll
        for (int ii = 0; ii < 16; ii++) {
            const int c = cg_e * 16 + ii;
            obase[(size_t)c * HW_SZ] = qsum[ii];
        }
    }
    // commit losses: block-reduce doubles, then 4 global atomics per block
#pragma unroll
    for (int q = 0; q < NQ; q++) atomicAdd(&sloss[q], lacc[q]);
    __syncthreads();
    if (tid < NQ) atomicAdd(&g_loss[tid], sloss[tid]);
}

// ---------------------------------------------------------------------------
// Final: write losses (runs after rvq on same stream)
// ---------------------------------------------------------------------------
__global__ void finish_kernel(float* __restrict__ out) {
    const int t = threadIdx.x;
    if (t < NQ)
        out[LOSS_OFF + t] = (float)(g_loss[t] * (1.0 / (131072.0 * 64.0)));
}

extern "C" void kernel_launch(void* const* d_in, const int* in_sizes, int n_in,
                              void* d_out, int out_size) {
    (void)in_sizes; (void)n_in; (void)out_size;
    const float* x  = (const float*)d_in[0];
    const float* cb = (const float*)d_in[1];
    float* out = (float*)d_out;

    prep_kernel<<<K_CB, 64>>>(cb);
    rvq_kernel<<<N_PTS / P_BLK, NTHR>>>(x, cb, out);
    finish_kernel<<<1, 32>>>(out);
}

// round 4
// speedup vs baseline: 1.7123x; 1.7123x over previous
#include <cuda_runtime.h>
#include <cstdint>

#define N_PTS   131072
#define C_DIM   64
#define K_CB    512
#define NQ      4
#define HW_SZ   16384
#define P_BLK   64
#define NTHR    512
#define KPT     8          // k's per thread
#define IDX_OFF 8388608
#define LOSS_OFF 8912896

// Scratch (allocation-free rule: __device__ globals)
__device__ float  g_G[K_CB * K_CB];   // Gram matrix cb @ cb.T (fast path only)
__device__ float  g_h[K_CB];          // 0.5 * ||cb_k||^2      (fast path only)
__device__ float  g_csq[K_CB];        // ||cb_k||^2, XLA-CPU vectorized-reduce order
__device__ double g_loss[NQ];         // double loss accumulators

// ---------------------------------------------------------------------------
// Precompute G, h, csq; zero loss accumulators.
// grid = 512 blocks x 512 threads. Block i: thread t computes G[i][t].
// ---------------------------------------------------------------------------
__global__ void prep_kernel(const float* __restrict__ cb) {
    __shared__ float ci[C_DIM];
    const int i = blockIdx.x;
    const int t = threadIdx.x;
    if (t < C_DIM) ci[t] = cb[i * C_DIM + t];
    __syncthreads();
    {
        const float4* row = (const float4*)(cb + t * C_DIM);
        float s = 0.f;
#pragma unroll
        for (int c4 = 0; c4 < 16; c4++) {
            float4 v = row[c4];
            s = fmaf(ci[4 * c4 + 0], v.x, s);
            s = fmaf(ci[4 * c4 + 1], v.y, s);
            s = fmaf(ci[4 * c4 + 2], v.z, s);
            s = fmaf(ci[4 * c4 + 3], v.w, s);
        }
        g_G[i * K_CB + t] = s;
        if (t == i) g_h[i] = 0.5f * s;
    }
    if (t == 0) {
        // csq exactly as XLA:CPU vectorized reduce (NEON width 4):
        // 4 strided lane accumulators, strict per-op rounding (mul+add,
        // no FMA), shuffle-halving horizontal sum: (L0+L2)+(L1+L3).
        float l0 = 0.f, l1 = 0.f, l2 = 0.f, l3 = 0.f;
        for (int j = 0; j < 16; j++) {
            float v0 = ci[4 * j + 0], v1 = ci[4 * j + 1];
            float v2 = ci[4 * j + 2], v3 = ci[4 * j + 3];
            l0 = __fadd_rn(l0, __fmul_rn(v0, v0));
            l1 = __fadd_rn(l1, __fmul_rn(v1, v1));
            l2 = __fadd_rn(l2, __fmul_rn(v2, v2));
            l3 = __fadd_rn(l3, __fmul_rn(v3, v3));
        }
        g_csq[i] = __fadd_rn(__fadd_rn(l0, l2), __fadd_rn(l1, l3));
    }
    if (i == 0 && t < NQ) g_loss[t] = 0.0;
}

// Orderable-float packing: larger float -> larger uint (monotone).
__device__ __forceinline__ unsigned ford(float f) {
    unsigned u = __float_as_uint(f);
    return (u & 0x80000000u) ? ~u : (u | 0x80000000u);
}
__device__ __forceinline__ float funord(unsigned s) {
    unsigned u = (s & 0x80000000u) ? (s ^ 0x80000000u) : ~s;
    return __uint_as_float(u);
}

// ---------------------------------------------------------------------------
// Main fused RVQ kernel. Block = 64 points x 512 codewords, 512 threads.
// Thread tile: 8 points (pg = tid&7) x 8 k's (kg = tid>>3) -> acc[8][8].
// Fast Gram-cascade scores filter candidates; exact reference-order
// arithmetic decides the argmin among candidates.
// ---------------------------------------------------------------------------
__global__ __launch_bounds__(NTHR, 1)
void rvq_kernel(const float* __restrict__ x, const float* __restrict__ cb,
                float* __restrict__ out) {
    __shared__ float rs[C_DIM][P_BLK];          // exact residual, [c][p]
    __shared__ float cbs[8][516];               // codebook c-chunk, [c'][k] padded
    __shared__ unsigned red1[P_BLK];            // fast max per point
    __shared__ unsigned long long redmin[P_BLK];// packed (dist,k) argmin
    __shared__ int    idxs[NQ][P_BLK];
    __shared__ double sloss[NQ];

    const int tid   = threadIdx.x;
    const int lane  = tid & 31;
    const int pg    = tid & 7;
    const int kg    = tid >> 3;                 // 0..63
    const int kbase = kg * KPT;
    const int n0    = blockIdx.x * P_BLK;
    const int b     = n0 / HW_SZ;               // 64 | HW, block never crosses b
    const int hw0   = n0 % HW_SZ;
    const float* xbase = x + (size_t)b * C_DIM * HW_SZ + hw0;

    if (tid < P_BLK) { red1[tid] = 0u; redmin[tid] = ~0ull; }
    if (tid < NQ)    sloss[tid] = 0.0;

    const int p_e  = tid & 63;       // elementwise-phase point
    const int cg_e = tid >> 6;       // elementwise-phase channel group (0..7)

    // ---- load x tile (coalesced over p); rs starts as x (exact residual) ----
#pragma unroll
    for (int ii = 0; ii < 8; ii++) {
        const int c = cg_e * 8 + ii;
        rs[c][p_e] = xbase[(size_t)c * HW_SZ + p_e];
    }

    // ---- fast scores: acc[k] = x.c - 0.5||c||^2 (candidate filter only) ----
    float acc[8][KPT];
    {
        float hv[KPT];
        ((float4*)hv)[0] = ((const float4*)(g_h + kbase))[0];
        ((float4*)hv)[1] = ((const float4*)(g_h + kbase))[1];
#pragma unroll
        for (int i = 0; i < 8; i++)
#pragma unroll
            for (int j = 0; j < KPT; j++)
                acc[i][j] = -hv[j];
    }
    for (int ct = 0; ct < 8; ct++) {
        __syncthreads();
        {   // load 8-channel slice of codebook, transposed to [c'][k]
            const int cp = tid & 7;
            const int k0 = tid >> 3;           // 0..63
#pragma unroll
            for (int it = 0; it < 8; it++) {
                const int k = k0 + 64 * it;
                cbs[cp][k] = cb[k * C_DIM + ct * 8 + cp];
            }
        }
        __syncthreads();
#pragma unroll
        for (int cc = 0; cc < 8; cc++) {
            const int c = ct * 8 + cc;
            float xa[8];
            ((float4*)xa)[0] = *((const float4*)&rs[c][pg * 8]);
            ((float4*)xa)[1] = *((const float4*)&rs[c][pg * 8 + 4]);
            float cv[KPT];
            ((float4*)cv)[0] = *((const float4*)&cbs[cc][kbase]);
            ((float4*)cv)[1] = *((const float4*)&cbs[cc][kbase + 4]);
#pragma unroll
            for (int i = 0; i < 8; i++)
#pragma unroll
                for (int j = 0; j < KPT; j++)
                    acc[i][j] = fmaf(xa[i], cv[j], acc[i][j]);
        }
    }
    __syncthreads();

    float qsum[8];                   // quantized accumulator (8 channels of p_e)
#pragma unroll
    for (int ii = 0; ii < 8; ii++) qsum[ii] = 0.f;

    // ---- 4 quantizer stages ----
#pragma unroll
    for (int q = 0; q < NQ; q++) {
        // A: fast local max per point; warp pre-reduce over kg (lanes share
        //    pg at xor 8,16), then one smem atomic per 8 lanes.
#pragma unroll
        for (int i = 0; i < 8; i++) {
            float bv = acc[i][0];
#pragma unroll
            for (int j = 1; j < KPT; j++) bv = fmaxf(bv, acc[i][j]);
            bv = fmaxf(bv, __shfl_xor_sync(0xffffffffu, bv, 8));
            bv = fmaxf(bv, __shfl_xor_sync(0xffffffffu, bv, 16));
            if (lane < 8) atomicMax(&red1[pg * 8 + i], ford(bv));
        }
        __syncthreads();

        // B: exact (reference-order) dist for windowed candidates
#pragma unroll
        for (int i = 0; i < 8; i++) {
            const int p = pg * 8 + i;
            const float thr = funord(red1[p]) - 0.01f;
#pragma unroll
            for (int j = 0; j < KPT; j++) {
                if (acc[i][j] >= thr) {
                    const int k = kbase + j;
                    const float* crow = cb + k * C_DIM;
                    float dot = 0.f;
#pragma unroll
                    for (int c = 0; c < C_DIM; c++)         // ascending-c seq FMA
                        dot = fmaf(rs[c][p], crow[c], dot);  // (Eigen gebp order)
                    float dist = __fsub_rn(g_csq[k], __fmul_rn(2.0f, dot));
                    unsigned long long pk =
                        ((unsigned long long)ford(dist) << 32) | (unsigned)k;
                    atomicMin(&redmin[p], pk);              // min dist, then min k
                }
            }
        }
        __syncthreads();

        // C: finalize pick, reset reducers
        if (tid < P_BLK) {
            idxs[q][tid] = (int)(unsigned)(redmin[tid] & 0xffffffffull);
            red1[tid]   = 0u;
            redmin[tid] = ~0ull;
        }
        __syncthreads();

        // D: exact elementwise update (replicates reference rounding chain)
        {
            const int k = idxs[q][p_e];
            const float* crow = cb + k * C_DIM;
            double ls = 0.0;
#pragma unroll
            for (int ii = 0; ii < 8; ii++) {
                const int c = cg_e * 8 + ii;
                const float cv = crow[c];
                const float r  = rs[c][p_e];
                const float d  = __fsub_rn(cv, r);          // quant - residual
                const float qst = __fadd_rn(r, d);          // straight-through
                qsum[ii] = __fadd_rn(qsum[ii], qst);        // quant_out += qst
                rs[c][p_e] = __fsub_rn(r, cv);              // residual -= quant
                const float sq = __fmul_rn(d, d);
                ls += (double)sq;
            }
            // warp-reduce the double, single atomic per warp
#pragma unroll
            for (int o = 16; o; o >>= 1)
                ls += __shfl_xor_sync(0xffffffffu, ls, o);
            if (lane == 0) atomicAdd(&sloss[q], ls);
        }

        // E: fast-score cascade for next stage: acc -= G[idx] row
        if (q < NQ - 1) {
#pragma unroll
            for (int i = 0; i < 8; i++) {
                const int row = idxs[q][pg * 8 + i];
                const float4* gr = (const float4*)(g_G + row * K_CB + kbase);
                float4 g0 = gr[0], g1 = gr[1];
                acc[i][0] -= g0.x; acc[i][1] -= g0.y;
                acc[i][2] -= g0.z; acc[i][3] -= g0.w;
                acc[i][4] -= g1.x; acc[i][5] -= g1.y;
                acc[i][6] -= g1.z; acc[i][7] -= g1.w;
            }
        }
        __syncthreads();
    }

    // ---- outputs ----
    // indices as float, coalesced: 256 threads cover 64 points x 4 stages
    if (tid < 256) {
        const int q = tid & 3, p = tid >> 2;
        out[IDX_OFF + (size_t)(n0 + p) * NQ + q] = (float)idxs[q][p];
    }
    // quantized in [B,C,H,W] layout (coalesced over p)
    {
        float* obase = out + (size_t)b * C_DIM * HW_SZ + hw0 + p_e;
#pragma unroll
        for (int ii = 0; ii < 8; ii++) {
            const int c = cg_e * 8 + ii;
            obase[(size_t)c * HW_SZ] = qsum[ii];
        }
    }
    // commit losses: 4 global atomics per block
    if (tid < NQ) atomicAdd(&g_loss[tid], sloss[tid]);
}

// ---------------------------------------------------------------------------
// Final: write losses (runs after rvq on same stream)
// ---------------------------------------------------------------------------
__global__ void finish_kernel(float* __restrict__ out) {
    const int t = threadIdx.x;
    if (t < NQ)
        out[LOSS_OFF + t] = (float)(g_loss[t] * (1.0 / (131072.0 * 64.0)));
}

extern "C" void kernel_launch(void* const* d_in, const int* in_sizes, int n_in,
                              void* d_out, int out_size) {
    (void)in_sizes; (void)n_in; (void)out_size;
    const float* x  = (const float*)d_in[0];
    const float* cb = (const float*)d_in[1];
    float* out = (float*)d_out;

    prep_kernel<<<K_CB, NTHR>>>(cb);
    rvq_kernel<<<N_PTS / P_BLK, NTHR>>>(x, cb, out);
    finish_kernel<<<1, 32>>>(out);
}

// round 5
// speedup vs baseline: 2.8836x; 1.6841x over previous
#include <cuda_runtime.h>
#include <cstdint>

#define N_PTS   131072
#define C_DIM   64
#define K_CB    512
#define NQ      4
#define HW_SZ   16384
#define P_BLK   32
#define NTHR    512
#define KPT     4          // k's per thread
#define PPT     8          // points per thread tile
#define NBLK    (N_PTS / P_BLK)
#define IDX_OFF 8388608
#define LOSS_OFF 8912896

// Scratch (allocation-free rule: __device__ globals)
__device__ float    g_G[K_CB * K_CB];  // Gram matrix cb @ cb.T (fast path only)
__device__ float    g_h[K_CB];         // 0.5 * ||cb_k||^2      (fast path only)
__device__ float    g_csq[K_CB];       // ||cb_k||^2, XLA-CPU vectorized-reduce order
__device__ double   g_loss[NQ];        // double loss accumulators
__device__ unsigned g_done = 0;        // last-block counter

// ---------------------------------------------------------------------------
// Precompute G, h, csq; zero loss accumulators.
// grid = 512 blocks x 512 threads. Block i: thread t computes G[i][t].
// ---------------------------------------------------------------------------
__global__ void prep_kernel(const float* __restrict__ cb) {
    __shared__ float ci[C_DIM];
    const int i = blockIdx.x;
    const int t = threadIdx.x;
    if (t < C_DIM) ci[t] = cb[i * C_DIM + t];
    __syncthreads();
    {
        const float4* row = (const float4*)(cb + t * C_DIM);
        float s = 0.f;
#pragma unroll
        for (int c4 = 0; c4 < 16; c4++) {
            float4 v = row[c4];
            s = fmaf(ci[4 * c4 + 0], v.x, s);
            s = fmaf(ci[4 * c4 + 1], v.y, s);
            s = fmaf(ci[4 * c4 + 2], v.z, s);
            s = fmaf(ci[4 * c4 + 3], v.w, s);
        }
        g_G[i * K_CB + t] = s;
        if (t == i) g_h[i] = 0.5f * s;
    }
    if (t == 0) {
        // csq exactly as XLA:CPU vectorized reduce (NEON width 4):
        // 4 strided lane accumulators, strict per-op rounding (mul+add,
        // no FMA), shuffle-halving horizontal sum: (L0+L2)+(L1+L3).
        float l0 = 0.f, l1 = 0.f, l2 = 0.f, l3 = 0.f;
        for (int j = 0; j < 16; j++) {
            float v0 = ci[4 * j + 0], v1 = ci[4 * j + 1];
            float v2 = ci[4 * j + 2], v3 = ci[4 * j + 3];
            l0 = __fadd_rn(l0, __fmul_rn(v0, v0));
            l1 = __fadd_rn(l1, __fmul_rn(v1, v1));
            l2 = __fadd_rn(l2, __fmul_rn(v2, v2));
            l3 = __fadd_rn(l3, __fmul_rn(v3, v3));
        }
        g_csq[i] = __fadd_rn(__fadd_rn(l0, l2), __fadd_rn(l1, l3));
    }
    if (i == 0 && t < NQ) g_loss[t] = 0.0;
}

// Orderable-float packing: larger float -> larger uint (monotone).
__device__ __forceinline__ unsigned ford(float f) {
    unsigned u = __float_as_uint(f);
    return (u & 0x80000000u) ? ~u : (u | 0x80000000u);
}
__device__ __forceinline__ float funord(unsigned s) {
    unsigned u = (s & 0x80000000u) ? (s ^ 0x80000000u) : ~s;
    return __uint_as_float(u);
}

// ---------------------------------------------------------------------------
// Main fused RVQ kernel. Block = 32 points x 512 codewords, 512 threads.
// Thread tile: 8 points (pg = tid&3, pts pg*8..pg*8+7) x 4 k's (kg = tid>>2).
// acc[8][4] = 32 regs -> no spill at the 128-reg cap.
// ---------------------------------------------------------------------------
__global__ __launch_bounds__(NTHR, 1)
void rvq_kernel(const float* __restrict__ x, const float* __restrict__ cb,
                float* __restrict__ out) {
    __shared__ float rs[C_DIM][P_BLK];          // exact residual, [c][p]
    __shared__ float cbs[8][516];               // codebook c-chunk, [c'][k] padded
    __shared__ unsigned red1[P_BLK];            // fast max per point
    __shared__ unsigned long long redmin[P_BLK];// packed (dist,k) argmin
    __shared__ int    idxs[NQ][P_BLK];
    __shared__ double sloss[NQ];

    const int tid   = threadIdx.x;
    const int lane  = tid & 31;
    const int pg    = tid & 3;                  // 0..3, 8 points each
    const int kg    = tid >> 2;                 // 0..127
    const int kbase = kg * KPT;
    const int n0    = blockIdx.x * P_BLK;
    const int b     = n0 / HW_SZ;               // 32 | HW, block never crosses b
    const int hw0   = n0 % HW_SZ;
    const float* xbase = x + (size_t)b * C_DIM * HW_SZ + hw0;

    if (tid < P_BLK) { red1[tid] = 0u; redmin[tid] = ~0ull; }
    if (tid < NQ)    sloss[tid] = 0.0;

    const int p_e  = tid & 31;       // elementwise-phase point (== lane)
    const int cg_e = tid >> 5;       // elementwise-phase channel group (0..15)

    // ---- load x tile (coalesced over p); rs starts as x (exact residual) ----
#pragma unroll
    for (int ii = 0; ii < 4; ii++) {
        const int c = cg_e * 4 + ii;
        rs[c][p_e] = xbase[(size_t)c * HW_SZ + p_e];
    }

    // ---- fast scores: acc[k] = x.c - 0.5||c||^2 (candidate filter only) ----
    float acc[PPT][KPT];
    {
        float4 hv = *((const float4*)(g_h + kbase));
#pragma unroll
        for (int i = 0; i < PPT; i++) {
            acc[i][0] = -hv.x; acc[i][1] = -hv.y;
            acc[i][2] = -hv.z; acc[i][3] = -hv.w;
        }
    }
    for (int ct = 0; ct < 8; ct++) {
        __syncthreads();
        {   // load 8-channel slice of codebook, transposed to [c'][k]
            const int cp = tid & 7;
            const int k0 = tid >> 3;            // 0..63
#pragma unroll
            for (int it = 0; it < 8; it++) {
                const int k = k0 + 64 * it;
                cbs[cp][k] = cb[k * C_DIM + ct * 8 + cp];
            }
        }
        __syncthreads();
#pragma unroll
        for (int cc = 0; cc < 8; cc++) {
            const int c = ct * 8 + cc;
            float xa[PPT];
            ((float4*)xa)[0] = *((const float4*)&rs[c][pg * 8]);
            ((float4*)xa)[1] = *((const float4*)&rs[c][pg * 8 + 4]);
            float4 cv = *((const float4*)&cbs[cc][kbase]);
#pragma unroll
            for (int i = 0; i < PPT; i++) {
                acc[i][0] = fmaf(xa[i], cv.x, acc[i][0]);
                acc[i][1] = fmaf(xa[i], cv.y, acc[i][1]);
                acc[i][2] = fmaf(xa[i], cv.z, acc[i][2]);
                acc[i][3] = fmaf(xa[i], cv.w, acc[i][3]);
            }
        }
    }
    __syncthreads();

    float qsum[4];                   // quantized accumulator (4 channels of p_e)
#pragma unroll
    for (int ii = 0; ii < 4; ii++) qsum[ii] = 0.f;

    // ---- 4 quantizer stages ----
#pragma unroll
    for (int q = 0; q < NQ; q++) {
        // A: fast local max per point; warp shfl pre-reduce over kg (lanes
        //    sharing pg differ in bits 2..4), then 1 atomic per (warp,point).
#pragma unroll
        for (int i = 0; i < PPT; i++) {
            float bv = fmaxf(fmaxf(acc[i][0], acc[i][1]),
                             fmaxf(acc[i][2], acc[i][3]));
            bv = fmaxf(bv, __shfl_xor_sync(0xffffffffu, bv, 4));
            bv = fmaxf(bv, __shfl_xor_sync(0xffffffffu, bv, 8));
            bv = fmaxf(bv, __shfl_xor_sync(0xffffffffu, bv, 16));
            if (lane < 4) atomicMax(&red1[pg * 8 + i], ford(bv));
        }
        __syncthreads();

        // B: exact (reference-order) dist for windowed candidates
#pragma unroll
        for (int i = 0; i < PPT; i++) {
            const int p = pg * 8 + i;
            const float thr = funord(red1[p]) - 0.01f;
#pragma unroll
            for (int j = 0; j < KPT; j++) {
                if (acc[i][j] >= thr) {
                    const int k = kbase + j;
                    const float4* c4 = (const float4*)(cb + k * C_DIM);
                    float dot = 0.f;
#pragma unroll 4
                    for (int g = 0; g < 16; g++) {           // ascending-c seq FMA
                        float4 v = c4[g];                     // (Eigen gebp order)
                        dot = fmaf(rs[4 * g + 0][p], v.x, dot);
                        dot = fmaf(rs[4 * g + 1][p], v.y, dot);
                        dot = fmaf(rs[4 * g + 2][p], v.z, dot);
                        dot = fmaf(rs[4 * g + 3][p], v.w, dot);
                    }
                    float dist = __fsub_rn(g_csq[k], __fmul_rn(2.0f, dot));
                    unsigned long long pk =
                        ((unsigned long long)ford(dist) << 32) | (unsigned)k;
                    atomicMin(&redmin[p], pk);               // min dist, then min k
                }
            }
        }
        __syncthreads();

        // C: finalize pick, reset reducers
        if (tid < P_BLK) {
            idxs[q][tid] = (int)(unsigned)(redmin[tid] & 0xffffffffull);
            red1[tid]   = 0u;
            redmin[tid] = ~0ull;
        }
        __syncthreads();

        // D: exact elementwise update (replicates reference rounding chain)
        {
            const int k = idxs[q][p_e];
            const float* crow = cb + k * C_DIM + cg_e * 4;
            double ls = 0.0;
#pragma unroll
            for (int ii = 0; ii < 4; ii++) {
                const int c = cg_e * 4 + ii;
                const float cv = crow[ii];
                const float r  = rs[c][p_e];
                const float d  = __fsub_rn(cv, r);          // quant - residual
                const float qst = __fadd_rn(r, d);          // straight-through
                qsum[ii] = __fadd_rn(qsum[ii], qst);        // quant_out += qst
                rs[c][p_e] = __fsub_rn(r, cv);              // residual -= quant
                const float sq = __fmul_rn(d, d);
                ls += (double)sq;
            }
            // warp-reduce the double, single smem atomic per warp
#pragma unroll
            for (int o = 16; o; o >>= 1)
                ls += __shfl_xor_sync(0xffffffffu, ls, o);
            if (lane == 0) atomicAdd(&sloss[q], ls);
        }

        // E: fast-score cascade for next stage: acc -= G[idx] row slice
        if (q < NQ - 1) {
#pragma unroll
            for (int i = 0; i < PPT; i++) {
                const int row = idxs[q][pg * 8 + i];
                float4 g = *((const float4*)(g_G + row * K_CB + kbase));
                acc[i][0] -= g.x; acc[i][1] -= g.y;
                acc[i][2] -= g.z; acc[i][3] -= g.w;
            }
        }
        __syncthreads();
    }

    // ---- outputs ----
    // indices as float, coalesced: 128 threads cover 32 points x 4 stages
    if (tid < P_BLK * NQ) {
        const int q = tid & 3, p = tid >> 2;
        out[IDX_OFF + (size_t)(n0 + p) * NQ + q] = (float)idxs[q][p];
    }
    // quantized in [B,C,H,W] layout (coalesced over p)
    {
        float* obase = out + (size_t)b * C_DIM * HW_SZ + hw0 + p_e;
#pragma unroll
        for (int ii = 0; ii < 4; ii++) {
            const int c = cg_e * 4 + ii;
            obase[(size_t)c * HW_SZ] = qsum[ii];
        }
    }
    // commit losses: 4 global atomics per block, last block writes output
    if (tid < NQ) atomicAdd(&g_loss[tid], sloss[tid]);
    __syncthreads();
    if (tid == 0) {
        __threadfence();
        unsigned t = atomicAdd(&g_done, 1u);
        if (t == (unsigned)(gridDim.x - 1)) {
            __threadfence();
            g_done = 0;                        // reset for next launch/replay
#pragma unroll
            for (int qq = 0; qq < NQ; qq++)
                out[LOSS_OFF + qq] =
                    (float)(g_loss[qq] * (1.0 / (131072.0 * 64.0)));
        }
    }
}

extern "C" void kernel_launch(void* const* d_in, const int* in_sizes, int n_in,
                              void* d_out, int out_size) {
    (void)in_sizes; (void)n_in; (void)out_size;
    const float* x  = (const float*)d_in[0];
    const float* cb = (const float*)d_in[1];
    float* out = (float*)d_out;

    prep_kernel<<<K_CB, NTHR>>>(cb);
    rvq_kernel<<<NBLK, NTHR>>>(x, cb, out);
}

// round 6
// speedup vs baseline: 4.9750x; 1.7253x over previous
#include <cuda_runtime.h>
#include <cstdint>

#define N_PTS   131072
#define C_DIM   64
#define K_CB    512
#define NQ      4
#define HW_SZ   16384
#define P_BLK   16
#define NTHR    256
#define KPT     4          // k's per thread
#define PPT     8          // points per thread tile
#define NBLK    (N_PTS / P_BLK)
#define WLCAP   512
#define IDX_OFF 8388608
#define LOSS_OFF 8912896

// Scratch (allocation-free rule: __device__ globals)
__device__ float    g_G[K_CB * K_CB];  // Gram matrix cb @ cb.T (fast path only)
__device__ float    g_h[K_CB];         // 0.5 * ||cb_k||^2      (fast path only)
__device__ float    g_csq[K_CB];       // ||cb_k||^2, XLA-CPU vectorized-reduce order
__device__ double   g_loss[NQ];        // double loss accumulators
__device__ unsigned g_done = 0;        // last-block counter

// ---------------------------------------------------------------------------
// Precompute G, h, csq; zero loss accumulators.
// ---------------------------------------------------------------------------
__global__ void prep_kernel(const float* __restrict__ cb) {
    __shared__ float ci[C_DIM];
    const int i = blockIdx.x;
    const int t = threadIdx.x;
    if (t < C_DIM) ci[t] = cb[i * C_DIM + t];
    __syncthreads();
    {
        const float4* row = (const float4*)(cb + t * C_DIM);
        float s = 0.f;
#pragma unroll
        for (int c4 = 0; c4 < 16; c4++) {
            float4 v = row[c4];
            s = fmaf(ci[4 * c4 + 0], v.x, s);
            s = fmaf(ci[4 * c4 + 1], v.y, s);
            s = fmaf(ci[4 * c4 + 2], v.z, s);
            s = fmaf(ci[4 * c4 + 3], v.w, s);
        }
        g_G[i * K_CB + t] = s;
        if (t == i) g_h[i] = 0.5f * s;
    }
    if (t == 0) {
        // csq exactly as XLA:CPU vectorized reduce (NEON width 4):
        // 4 strided lane accumulators, strict per-op rounding (mul+add,
        // no FMA), shuffle-halving horizontal sum: (L0+L2)+(L1+L3).
        float l0 = 0.f, l1 = 0.f, l2 = 0.f, l3 = 0.f;
        for (int j = 0; j < 16; j++) {
            float v0 = ci[4 * j + 0], v1 = ci[4 * j + 1];
            float v2 = ci[4 * j + 2], v3 = ci[4 * j + 3];
            l0 = __fadd_rn(l0, __fmul_rn(v0, v0));
            l1 = __fadd_rn(l1, __fmul_rn(v1, v1));
            l2 = __fadd_rn(l2, __fmul_rn(v2, v2));
            l3 = __fadd_rn(l3, __fmul_rn(v3, v3));
        }
        g_csq[i] = __fadd_rn(__fadd_rn(l0, l2), __fadd_rn(l1, l3));
    }
    if (i == 0 && t < NQ) g_loss[t] = 0.0;
}

// Orderable-float packing: larger float -> larger uint (monotone).
__device__ __forceinline__ unsigned ford(float f) {
    unsigned u = __float_as_uint(f);
    return (u & 0x80000000u) ? ~u : (u | 0x80000000u);
}
__device__ __forceinline__ float funord(unsigned s) {
    unsigned u = (s & 0x80000000u) ? (s ^ 0x80000000u) : ~s;
    return __uint_as_float(u);
}

// ---------------------------------------------------------------------------
// Main fused RVQ kernel. Block = 16 points x 512 codewords, 256 threads,
// 3 blocks/SM. Thread tile: 8 points (pg = tid&1) x 4 k's (kg = tid>>1).
// acc[8][4] = 32 regs. Windowed candidates go to a smem worklist; each
// candidate's exact reference-order dot runs on one thread.
// ---------------------------------------------------------------------------
__global__ __launch_bounds__(NTHR, 3)
void rvq_kernel(const float* __restrict__ x, const float* __restrict__ cb,
                float* __restrict__ out) {
    __shared__ float rs[C_DIM][P_BLK];          // exact residual, [c][p]
    __shared__ float cbs[8][516];               // codebook c-chunk, [c'][k] padded
    __shared__ unsigned red1[P_BLK];            // fast max per point
    __shared__ unsigned long long redmin[P_BLK];// packed (dist,k) argmin
    __shared__ int    idxs[NQ][P_BLK];
    __shared__ double sloss[NQ];
    __shared__ int    wl[WLCAP];                // candidate worklist (p<<9|k)
    __shared__ int    wl_n;

    const int tid   = threadIdx.x;
    const int lane  = tid & 31;
    const int pg    = tid & 1;                  // 0..1, 8 points each
    const int kg    = tid >> 1;                 // 0..127
    const int kbase = kg * KPT;
    const int n0    = blockIdx.x * P_BLK;
    const int b     = n0 / HW_SZ;               // 16 | HW, block never crosses b
    const int hw0   = n0 % HW_SZ;
    const float* xbase = x + (size_t)b * C_DIM * HW_SZ + hw0;

    if (tid < P_BLK) { red1[tid] = 0u; redmin[tid] = ~0ull; }
    if (tid < NQ)    sloss[tid] = 0.0;
    if (tid == 0)    wl_n = 0;

    const int p_e  = tid & 15;       // elementwise-phase point
    const int cg_e = tid >> 4;       // elementwise-phase channel group (0..15)

    // ---- load x tile (coalesced over p); rs starts as x (exact residual) ----
#pragma unroll
    for (int ii = 0; ii < 4; ii++) {
        const int c = cg_e * 4 + ii;
        rs[c][p_e] = xbase[(size_t)c * HW_SZ + p_e];
    }

    // ---- fast scores: acc[k] = x.c - 0.5||c||^2 (candidate filter only) ----
    float acc[PPT][KPT];
    {
        float4 hv = *((const float4*)(g_h + kbase));
#pragma unroll
        for (int i = 0; i < PPT; i++) {
            acc[i][0] = -hv.x; acc[i][1] = -hv.y;
            acc[i][2] = -hv.z; acc[i][3] = -hv.w;
        }
    }
    for (int ct = 0; ct < 8; ct++) {
        __syncthreads();
        {   // load 8-channel slice of codebook, transposed to [c'][k]
            const int cp = tid & 7;
            const int k0 = tid >> 3;            // 0..31
#pragma unroll
            for (int it = 0; it < 16; it++) {
                const int k = k0 + 32 * it;
                cbs[cp][k] = cb[k * C_DIM + ct * 8 + cp];
            }
        }
        __syncthreads();
#pragma unroll
        for (int cc = 0; cc < 8; cc++) {
            const int c = ct * 8 + cc;
            float xa[PPT];
            ((float4*)xa)[0] = *((const float4*)&rs[c][pg * 8]);
            ((float4*)xa)[1] = *((const float4*)&rs[c][pg * 8 + 4]);
            float4 cv = *((const float4*)&cbs[cc][kbase]);
#pragma unroll
            for (int i = 0; i < PPT; i++) {
                acc[i][0] = fmaf(xa[i], cv.x, acc[i][0]);
                acc[i][1] = fmaf(xa[i], cv.y, acc[i][1]);
                acc[i][2] = fmaf(xa[i], cv.z, acc[i][2]);
                acc[i][3] = fmaf(xa[i], cv.w, acc[i][3]);
            }
        }
    }
    __syncthreads();

    float qsum[4];                   // quantized accumulator (4 channels of p_e)
#pragma unroll
    for (int ii = 0; ii < 4; ii++) qsum[ii] = 0.f;

    // ---- 4 quantizer stages ----
#pragma unroll
    for (int q = 0; q < NQ; q++) {
        // A: fast local max per point; shfl pre-reduce over kg (same-pg lanes
        //    differ in bits 1..4), then one smem atomic per (warp,point).
#pragma unroll
        for (int i = 0; i < PPT; i++) {
            float bv = fmaxf(fmaxf(acc[i][0], acc[i][1]),
                             fmaxf(acc[i][2], acc[i][3]));
            bv = fmaxf(bv, __shfl_xor_sync(0xffffffffu, bv, 2));
            bv = fmaxf(bv, __shfl_xor_sync(0xffffffffu, bv, 4));
            bv = fmaxf(bv, __shfl_xor_sync(0xffffffffu, bv, 8));
            bv = fmaxf(bv, __shfl_xor_sync(0xffffffffu, bv, 16));
            if (lane < 2) atomicMax(&red1[pg * 8 + i], ford(bv));
        }
        __syncthreads();

        // B1: scan tile, push windowed candidates to worklist
#pragma unroll
        for (int i = 0; i < PPT; i++) {
            const int p = pg * 8 + i;
            const float thr = funord(red1[p]) - 0.01f;
#pragma unroll
            for (int j = 0; j < KPT; j++) {
                if (acc[i][j] >= thr) {
                    int pos = atomicAdd(&wl_n, 1);
                    if (pos < WLCAP) wl[pos] = (p << 9) | (kbase + j);
                }
            }
        }
        __syncthreads();

        // B2: exact (reference-order) dist per candidate, one thread each
        {
            const int wn = (wl_n < WLCAP) ? wl_n : WLCAP;
            for (int t = tid; t < wn; t += NTHR) {
                const int e = wl[t];
                const int p = e >> 9;
                const int k = e & 511;
                const float4* c4 = (const float4*)(cb + k * C_DIM);
                float dot = 0.f;
#pragma unroll 4
                for (int g = 0; g < 16; g++) {           // ascending-c seq FMA
                    float4 v = c4[g];                     // (Eigen gebp order)
                    dot = fmaf(rs[4 * g + 0][p], v.x, dot);
                    dot = fmaf(rs[4 * g + 1][p], v.y, dot);
                    dot = fmaf(rs[4 * g + 2][p], v.z, dot);
                    dot = fmaf(rs[4 * g + 3][p], v.w, dot);
                }
                float dist = __fsub_rn(g_csq[k], __fmul_rn(2.0f, dot));
                unsigned long long pk =
                    ((unsigned long long)ford(dist) << 32) | (unsigned)k;
                atomicMin(&redmin[p], pk);               // min dist, then min k
            }
        }
        __syncthreads();

        // C: finalize pick, reset reducers + worklist
        if (tid < P_BLK) {
            idxs[q][tid] = (int)(unsigned)(redmin[tid] & 0xffffffffull);
            red1[tid]   = 0u;
            redmin[tid] = ~0ull;
        }
        if (tid == 0) wl_n = 0;
        __syncthreads();

        // D: exact elementwise update (replicates reference rounding chain)
        {
            const int k = idxs[q][p_e];
            const float* crow = cb + k * C_DIM + cg_e * 4;
            double ls = 0.0;
#pragma unroll
            for (int ii = 0; ii < 4; ii++) {
                const int c = cg_e * 4 + ii;
                const float cv = crow[ii];
                const float r  = rs[c][p_e];
                const float d  = __fsub_rn(cv, r);          // quant - residual
                const float qst = __fadd_rn(r, d);          // straight-through
                qsum[ii] = __fadd_rn(qsum[ii], qst);        // quant_out += qst
                rs[c][p_e] = __fsub_rn(r, cv);              // residual -= quant
                const float sq = __fmul_rn(d, d);
                ls += (double)sq;
            }
            // warp-reduce the double, single smem atomic per warp
#pragma unroll
            for (int o = 16; o; o >>= 1)
                ls += __shfl_xor_sync(0xffffffffu, ls, o);
            if (lane == 0) atomicAdd(&sloss[q], ls);
        }

        // E: fast-score cascade for next stage: acc -= G[idx] row slice
        if (q < NQ - 1) {
#pragma unroll
            for (int i = 0; i < PPT; i++) {
                const int row = idxs[q][pg * 8 + i];
                float4 g = *((const float4*)(g_G + row * K_CB + kbase));
                acc[i][0] -= g.x; acc[i][1] -= g.y;
                acc[i][2] -= g.z; acc[i][3] -= g.w;
            }
        }
        __syncthreads();
    }

    // ---- outputs ----
    // indices as float, coalesced: 64 threads cover 16 points x 4 stages
    if (tid < P_BLK * NQ) {
        const int q = tid & 3, p = tid >> 2;
        out[IDX_OFF + (size_t)(n0 + p) * NQ + q] = (float)idxs[q][p];
    }
    // quantized in [B,C,H,W] layout (coalesced over p)
    {
        float* obase = out + (size_t)b * C_DIM * HW_SZ + hw0 + p_e;
#pragma unroll
        for (int ii = 0; ii < 4; ii++) {
            const int c = cg_e * 4 + ii;
            obase[(size_t)c * HW_SZ] = qsum[ii];
        }
    }
    // commit losses: 4 global atomics per block, last block writes output
    if (tid < NQ) atomicAdd(&g_loss[tid], sloss[tid]);
    __syncthreads();
    if (tid == 0) {
        __threadfence();
        unsigned t = atomicAdd(&g_done, 1u);
        if (t == (unsigned)(gridDim.x - 1)) {
            __threadfence();
            g_done = 0;                        // reset for next launch/replay
#pragma unroll
            for (int qq = 0; qq < NQ; qq++)
                out[LOSS_OFF + qq] =
                    (float)(g_loss[qq] * (1.0 / (131072.0 * 64.0)));
        }
    }
}

extern "C" void kernel_launch(void* const* d_in, const int* in_sizes, int n_in,
                              void* d_out, int out_size) {
    (void)in_sizes; (void)n_in; (void)out_size;
    const float* x  = (const float*)d_in[0];
    const float* cb = (const float*)d_in[1];
    float* out = (float*)d_out;

    prep_kernel<<<K_CB, 512>>>(cb);
    rvq_kernel<<<NBLK, NTHR>>>(x, cb, out);
}